// round 1
// baseline (speedup 1.0000x reference)
#include <cuda_runtime.h>
#include <math.h>

#define Bn 4
#define Cc 256
#define Onc 256
#define Hh 64
#define Ww 64
#define Kk 9
#define HW 4096

// Scratch (static device arrays — no allocation)
__device__ float g_buf1[Bn * Cc * HW];          // layer0 output
__device__ float g_buf2[Bn * Cc * HW];          // layer1 output
__device__ float g_ys[Bn * HW * Kk];
__device__ float g_xs[Bn * HW * Kk];
__device__ float g_ms[Bn * HW * Kk];
__device__ float g_wT[3 * Cc * Kk * Onc];       // transposed weights [l][c][k][o]

// ---------------------------------------------------------------------------
// Transpose main-conv weights: [O][C][3][3] -> [C][9][O] for coalesced staging
// ---------------------------------------------------------------------------
__global__ void transpose_w_kernel(const float* __restrict__ w, float* __restrict__ wT)
{
    int idx = blockIdx.x * blockDim.x + threadIdx.x;
    if (idx >= Cc * Kk * Onc) return;
    int o = idx & (Onc - 1);
    int k = (idx >> 8) % Kk;
    int c = idx / (Kk * Onc);
    wT[idx] = w[((size_t)o * Cc + c) * Kk + k];
}

// ---------------------------------------------------------------------------
// Kernel A: offset conv (C->27, 3x3, pad 1) fused with coordinate/mask compute.
// Block: 128 threads, tile = 8 rows x 32 cols (each thread computes 2 adjacent
// pixels, 27 channels). Grid: (16 tiles, B).
// ---------------------------------------------------------------------------
__global__ __launch_bounds__(128) void offset_conv_kernel(
    const float* __restrict__ x,
    const float* __restrict__ w_off,
    const float* __restrict__ b_off)
{
    __shared__ float tile[10 * 34];
    __shared__ float wsm[27 * 9];

    int b   = blockIdx.y;
    int t   = blockIdx.x;            // 0..15
    int ty0 = (t >> 1) * 8;          // row-tile origin
    int tx0 = (t & 1) * 32;          // col-tile origin
    int tid = threadIdx.x;
    int ty  = tid >> 4;              // 0..7
    int tx  = (tid & 15) * 2;        // 0,2,...,30

    float acc[27][2];
#pragma unroll
    for (int oc = 0; oc < 27; oc++) {
        float bv = b_off[oc];
        acc[oc][0] = bv;
        acc[oc][1] = bv;
    }

    for (int ic = 0; ic < Cc; ic++) {
        const float* xp = x + ((size_t)(b * Cc + ic)) * HW;
        // cooperative load of 10x34 input tile (with zero halo)
        for (int i = tid; i < 340; i += 128) {
            int r  = i / 34;
            int cc = i - r * 34;
            int gy = ty0 - 1 + r;
            int gx = tx0 - 1 + cc;
            float v = 0.f;
            if (gy >= 0 && gy < Hh && gx >= 0 && gx < Ww)
                v = __ldg(xp + gy * Ww + gx);
            tile[i] = v;
        }
        // cooperative load of 27x9 weights for this ic
        for (int i = tid; i < 243; i += 128) {
            int oc  = i / 9;
            int tap = i - oc * 9;
            wsm[i] = __ldg(w_off + ((size_t)oc * Cc + ic) * 9 + tap);
        }
        __syncthreads();

        float xr[3][4];
#pragma unroll
        for (int r = 0; r < 3; r++)
#pragma unroll
            for (int c2 = 0; c2 < 4; c2++)
                xr[r][c2] = tile[(ty + r) * 34 + tx + c2];

#pragma unroll
        for (int oc = 0; oc < 27; oc++) {
#pragma unroll
            for (int tap = 0; tap < 9; tap++) {
                float wv = wsm[oc * 9 + tap];
                int r  = tap / 3;
                int c2 = tap % 3;
                acc[oc][0] += wv * xr[r][c2];
                acc[oc][1] += wv * xr[r][c2 + 1];
            }
        }
        __syncthreads();
    }

    // epilogue: compute sampling coordinates + sigmoid(mask)
    int h = ty0 + ty;
#pragma unroll
    for (int px = 0; px < 2; px++) {
        int w = tx0 + tx + px;
        size_t base = ((size_t)b * HW + h * Ww + w) * Kk;
#pragma unroll
        for (int k = 0; k < Kk; k++) {
            float dy = acc[2 * k][px];
            float dx = acc[2 * k + 1][px];
            float mm = 1.f / (1.f + expf(-acc[18 + k][px]));
            g_ys[base + k] = (float)h + (float)(k / 3 - 1) + dy;
            g_xs[base + k] = (float)w + (float)(k % 3 - 1) + dx;
            g_ms[base + k] = mm;
        }
    }
}

// ---------------------------------------------------------------------------
// Kernel B: fused bilinear sampling + GEMM + bias + ReLU.
// Block: 256 threads, computes [256 outputs] x [8x8 pixel tile].
// Each thread: 8(o) x 8(p) register tile.
// Grid: (64 pixel tiles, B).
// ---------------------------------------------------------------------------
__global__ __launch_bounds__(256, 2) void dcn_kernel(
    const float* __restrict__ x,
    const float* __restrict__ wT,     // [C][9][O]
    const float* __restrict__ bias,
    float* __restrict__ out)
{
    __shared__ float4 swgt[576];      // premultiplied bilinear weights (incl. mask)
    __shared__ int4   sidx[576];      // clamped gather indices within plane
    __shared__ float  ssm[9 * 64];    // sampled values [k][p]
    __shared__ float  wsm[9 * 256];   // weights [k][o]

    int b   = blockIdx.y;
    int t   = blockIdx.x;             // 0..63
    int py0 = (t >> 3) * 8;
    int px0 = (t & 7) * 8;
    int tid = threadIdx.x;

    // Precompute per-(k,p) gather indices and weights (once per block).
    // Layout: i = k*64 + p, p = row*8 + col within the 8x8 tile.
    for (int i = tid; i < 576; i += 256) {
        int p  = i & 63;
        int k  = i >> 6;
        int gy = py0 + (p >> 3);
        int gx = px0 + (p & 7);
        size_t cb = ((size_t)b * HW + gy * Ww + gx) * Kk + k;
        float ysv = g_ys[cb];
        float xsv = g_xs[cb];
        float mv  = g_ms[cb];
        float y0f = floorf(ysv), x0f = floorf(xsv);
        float wy = ysv - y0f, wx = xsv - x0f;
        int y0 = (int)y0f, x0 = (int)x0f;
        int y1 = y0 + 1, x1 = x0 + 1;
        bool vy0 = (y0 >= 0) && (y0 < Hh);
        bool vy1 = (y1 >= 0) && (y1 < Hh);
        bool vx0 = (x0 >= 0) && (x0 < Ww);
        bool vx1 = (x1 >= 0) && (x1 < Ww);
        int y0c = min(max(y0, 0), Hh - 1), y1c = min(max(y1, 0), Hh - 1);
        int x0c = min(max(x0, 0), Ww - 1), x1c = min(max(x1, 0), Ww - 1);
        float4 wv;
        wv.x = (vy0 && vx0) ? mv * (1.f - wy) * (1.f - wx) : 0.f;
        wv.y = (vy0 && vx1) ? mv * (1.f - wy) * wx         : 0.f;
        wv.z = (vy1 && vx0) ? mv * wy * (1.f - wx)         : 0.f;
        wv.w = (vy1 && vx1) ? mv * wy * wx                 : 0.f;
        swgt[i] = wv;
        int4 iv;
        iv.x = y0c * Ww + x0c;
        iv.y = y0c * Ww + x1c;
        iv.z = y1c * Ww + x0c;
        iv.w = y1c * Ww + x1c;
        sidx[i] = iv;
    }
    __syncthreads();

    int to = tid >> 3;   // 0..31 -> output block to*8
    int tp = tid & 7;    // 0..7  -> pixel-row within tile

    float acc[8][8];
#pragma unroll
    for (int i = 0; i < 8; i++)
#pragma unroll
        for (int j = 0; j < 8; j++) acc[i][j] = 0.f;

    for (int c = 0; c < Cc; c++) {
        const float* xp = x + ((size_t)(b * Cc + c)) * HW;
        // stage sampled values s[k][p]
        for (int i = tid; i < 576; i += 256) {
            float4 wv = swgt[i];
            int4   iv = sidx[i];
            float s = wv.x * __ldg(xp + iv.x) + wv.y * __ldg(xp + iv.y)
                    + wv.z * __ldg(xp + iv.z) + wv.w * __ldg(xp + iv.w);
            ssm[i] = s;
        }
        // stage weights w[k][o] for this c (coalesced from transposed copy)
        {
            const float* wp = wT + (size_t)c * (Kk * Onc);
#pragma unroll
            for (int k = 0; k < 9; k++)
                wsm[k * 256 + tid] = __ldg(wp + k * 256 + tid);
        }
        __syncthreads();

#pragma unroll
        for (int k = 0; k < 9; k++) {
            float4 wA = *(const float4*)(wsm + k * 256 + to * 8);
            float4 wB = *(const float4*)(wsm + k * 256 + to * 8 + 4);
            float4 sA = *(const float4*)(ssm + k * 64 + tp * 8);
            float4 sB = *(const float4*)(ssm + k * 64 + tp * 8 + 4);
            float wv[8] = {wA.x, wA.y, wA.z, wA.w, wB.x, wB.y, wB.z, wB.w};
            float sv[8] = {sA.x, sA.y, sA.z, sA.w, sB.x, sB.y, sB.z, sB.w};
#pragma unroll
            for (int i = 0; i < 8; i++)
#pragma unroll
                for (int j = 0; j < 8; j++)
                    acc[i][j] += wv[i] * sv[j];
        }
        __syncthreads();
    }

    // epilogue: bias + ReLU, write [B,O,H,W]
#pragma unroll
    for (int i = 0; i < 8; i++) {
        int o = to * 8 + i;
        float bv = __ldg(bias + o);
        float* op = out + ((size_t)(b * Onc + o) * Hh + (py0 + tp)) * Ww + px0;
#pragma unroll
        for (int j = 0; j < 8; j++) {
            float v = acc[i][j] + bv;
            op[j] = v > 0.f ? v : 0.f;
        }
    }
}

// ---------------------------------------------------------------------------
// Launch
// ---------------------------------------------------------------------------
extern "C" void kernel_launch(void* const* d_in, const int* in_sizes, int n_in,
                              void* d_out, int out_size)
{
    const float* x = (const float*)d_in[0];
    const float* w_off[3] = {(const float*)d_in[1], (const float*)d_in[5], (const float*)d_in[9]};
    const float* b_off[3] = {(const float*)d_in[2], (const float*)d_in[6], (const float*)d_in[10]};
    const float* wq[3]    = {(const float*)d_in[3], (const float*)d_in[7], (const float*)d_in[11]};
    const float* bias[3]  = {(const float*)d_in[4], (const float*)d_in[8], (const float*)d_in[12]};

    float *buf1, *buf2, *wT;
    cudaGetSymbolAddress((void**)&buf1, g_buf1);
    cudaGetSymbolAddress((void**)&buf2, g_buf2);
    cudaGetSymbolAddress((void**)&wT, g_wT);

    // Transpose main weights for all 3 layers
    for (int l = 0; l < 3; l++) {
        transpose_w_kernel<<<(Cc * Kk * Onc + 255) / 256, 256>>>(wq[l], wT + (size_t)l * Cc * Kk * Onc);
    }

    const float* src[3] = {x, buf1, buf2};
    float*       dst[3] = {buf1, buf2, (float*)d_out};

    for (int l = 0; l < 3; l++) {
        offset_conv_kernel<<<dim3(16, Bn), 128>>>(src[l], w_off[l], b_off[l]);
        dcn_kernel<<<dim3(64, Bn), 256>>>(src[l], wT + (size_t)l * Cc * Kk * Onc, bias[l], dst[l]);
    }
}

// round 2
// speedup vs baseline: 1.4048x; 1.4048x over previous
#include <cuda_runtime.h>
#include <math.h>

#define Bn 4
#define Cc 256
#define Onc 256
#define Hh 64
#define Ww 64
#define Kk 9
#define HW 4096

// Scratch (static device arrays — no allocation)
__device__ float g_buf1[Bn * Cc * HW];          // layer0 output
__device__ float g_buf2[Bn * Cc * HW];          // layer1 output
__device__ float g_wT[3 * Cc * Kk * Onc];       // transposed weights [l][c][k][o]

// ---------------------------------------------------------------------------
// Transpose main-conv weights: [O][C][3][3] -> [C][9][O] for coalesced staging
// ---------------------------------------------------------------------------
__global__ void transpose_w_kernel(const float* __restrict__ w, float* __restrict__ wT)
{
    int idx = blockIdx.x * blockDim.x + threadIdx.x;
    if (idx >= Cc * Kk * Onc) return;
    int o = idx & (Onc - 1);
    int k = (idx >> 8) % Kk;
    int c = idx / (Kk * Onc);
    wT[idx] = w[((size_t)o * Cc + c) * Kk + k];
}

// ---------------------------------------------------------------------------
// Fully fused kernel: offset conv (phase 1) + bilinear sampling + GEMM +
// bias + ReLU (phase 2).
// Block: 256 threads. Tile: 8x8 pixels x 256 outputs. Grid: (64, B).
//
// Phase 1: 256 threads = 64 pixels x 4 channel-groups. Each thread
// accumulates 27 offset-conv outputs over its 64-channel subset; partials
// are reduced through shared memory, then converted to premultiplied
// bilinear gather weights + clamped indices (stored once per block).
//
// Phase 2: identical to the proven R1 GEMM loop: per channel, stage 9x64
// sampled values + 9x256 weights, 8x8 register-tile FFMA.
// ---------------------------------------------------------------------------
__global__ __launch_bounds__(256, 2) void dcn_fused_kernel(
    const float* __restrict__ x,
    const float* __restrict__ w_off,   // [27][C][3][3]
    const float* __restrict__ b_off,   // [27]
    const float* __restrict__ wT,      // [C][9][O]
    const float* __restrict__ bias,    // [O]
    float* __restrict__ out)
{
    __shared__ union {
        struct {
            float om[4][64][28];    // per-group partial offset-conv outputs
            float xs[4][120];       // 10x12 halo tile per channel-group
            float wo[4][9][28];     // offset weights transposed [g][tap][oc]
        } p1;
        struct {
            float4 swgt[576];       // premultiplied bilinear weights (incl. mask)
            int4   sidx[576];       // clamped gather indices
        } p2;
    } u;
    __shared__ float ssm[9 * 64];    // sampled values [k][p]
    __shared__ float wsm[9 * 256];   // weights [k][o]

    int b   = blockIdx.y;
    int t   = blockIdx.x;             // 0..63
    int py0 = (t >> 3) * 8;
    int px0 = (t & 7) * 8;
    int tid = threadIdx.x;

    // ======================== Phase 1: offset conv ========================
    {
        int p   = tid & 63;           // pixel within tile
        int g   = tid >> 6;           // channel group 0..3
        int ppy = p >> 3;
        int ppx = p & 7;

        float aoff[27];
#pragma unroll
        for (int i = 0; i < 27; i++) aoff[i] = 0.f;

        for (int s = 0; s < 64; s++) {
            __syncthreads();
            // stage 4 channels' 10x10 halo tiles (zero-padded at borders)
            for (int i = tid; i < 400; i += 256) {
                int gg = i / 100;
                int r  = (i % 100) / 10;
                int cc = (i % 100) % 10;
                int c  = s * 4 + gg;
                int gy = py0 - 1 + r;
                int gx = px0 - 1 + cc;
                float v = 0.f;
                if (gy >= 0 && gy < Hh && gx >= 0 && gx < Ww)
                    v = __ldg(x + ((size_t)(b * Cc + c)) * HW + gy * Ww + gx);
                u.p1.xs[gg][r * 12 + cc] = v;
            }
            // stage 4 channels' offset weights, transposed to [tap][oc]
            for (int i = tid; i < 972; i += 256) {
                int gg  = i / 243;
                int rem = i - gg * 243;
                int oc  = rem / 9;
                int tap = rem - oc * 9;
                int c   = s * 4 + gg;
                u.p1.wo[gg][tap][oc] = __ldg(w_off + ((size_t)oc * Cc + c) * 9 + tap);
            }
            __syncthreads();

            float xv[9];
#pragma unroll
            for (int r = 0; r < 3; r++)
#pragma unroll
                for (int cc = 0; cc < 3; cc++)
                    xv[r * 3 + cc] = u.p1.xs[g][(ppy + r) * 12 + ppx + cc];

#pragma unroll
            for (int tap = 0; tap < 9; tap++) {
                float xt = xv[tap];
                const float* wrow = u.p1.wo[g][tap];
#pragma unroll
                for (int oc = 0; oc < 27; oc++)
                    aoff[oc] += xt * wrow[oc];
            }
        }
        __syncthreads();
#pragma unroll
        for (int i = 0; i < 27; i++) u.p1.om[g][p][i] = aoff[i];
        __syncthreads();
    }

    // ============= Coordinate / gather-weight precompute =============
    {
        float4 rw[3];
        int4   ri[3];
#pragma unroll
        for (int j = 0; j < 3; j++) {
            int i = tid + j * 256;
            if (i < 576) {
                int p = i & 63;
                int k = i >> 6;
                int gy = py0 + (p >> 3);
                int gx = px0 + (p & 7);
                float dy = __ldg(b_off + 2 * k)     + u.p1.om[0][p][2 * k]     + u.p1.om[1][p][2 * k]
                                                    + u.p1.om[2][p][2 * k]     + u.p1.om[3][p][2 * k];
                float dx = __ldg(b_off + 2 * k + 1) + u.p1.om[0][p][2 * k + 1] + u.p1.om[1][p][2 * k + 1]
                                                    + u.p1.om[2][p][2 * k + 1] + u.p1.om[3][p][2 * k + 1];
                float mr = __ldg(b_off + 18 + k)    + u.p1.om[0][p][18 + k]    + u.p1.om[1][p][18 + k]
                                                    + u.p1.om[2][p][18 + k]    + u.p1.om[3][p][18 + k];
                float mv = 1.f / (1.f + expf(-mr));
                float ysv = (float)gy + (float)(k / 3 - 1) + dy;
                float xsv = (float)gx + (float)(k % 3 - 1) + dx;
                float y0f = floorf(ysv), x0f = floorf(xsv);
                float wy = ysv - y0f, wx = xsv - x0f;
                int y0 = (int)y0f, x0 = (int)x0f;
                int y1 = y0 + 1, x1 = x0 + 1;
                bool vy0 = (y0 >= 0) && (y0 < Hh);
                bool vy1 = (y1 >= 0) && (y1 < Hh);
                bool vx0 = (x0 >= 0) && (x0 < Ww);
                bool vx1 = (x1 >= 0) && (x1 < Ww);
                int y0c = min(max(y0, 0), Hh - 1), y1c = min(max(y1, 0), Hh - 1);
                int x0c = min(max(x0, 0), Ww - 1), x1c = min(max(x1, 0), Ww - 1);
                float4 wv;
                wv.x = (vy0 && vx0) ? mv * (1.f - wy) * (1.f - wx) : 0.f;
                wv.y = (vy0 && vx1) ? mv * (1.f - wy) * wx         : 0.f;
                wv.z = (vy1 && vx0) ? mv * wy * (1.f - wx)         : 0.f;
                wv.w = (vy1 && vx1) ? mv * wy * wx                 : 0.f;
                rw[j] = wv;
                int4 iv;
                iv.x = y0c * Ww + x0c;
                iv.y = y0c * Ww + x1c;
                iv.z = y1c * Ww + x0c;
                iv.w = y1c * Ww + x1c;
                ri[j] = iv;
            }
        }
        __syncthreads();   // all om reads done before overwriting union with p2
#pragma unroll
        for (int j = 0; j < 3; j++) {
            int i = tid + j * 256;
            if (i < 576) {
                u.p2.swgt[i] = rw[j];
                u.p2.sidx[i] = ri[j];
            }
        }
        __syncthreads();
    }

    // ================= Phase 2: sampling + GEMM + epilogue =================
    int to = tid >> 3;   // 0..31 -> output block to*8
    int tp = tid & 7;    // 0..7  -> pixel-row within tile

    float acc[8][8];
#pragma unroll
    for (int i = 0; i < 8; i++)
#pragma unroll
        for (int j = 0; j < 8; j++) acc[i][j] = 0.f;

    for (int c = 0; c < Cc; c++) {
        const float* xp = x + ((size_t)(b * Cc + c)) * HW;
        // stage sampled values s[k][p]
        for (int i = tid; i < 576; i += 256) {
            float4 wv = u.p2.swgt[i];
            int4   iv = u.p2.sidx[i];
            float s = wv.x * __ldg(xp + iv.x) + wv.y * __ldg(xp + iv.y)
                    + wv.z * __ldg(xp + iv.z) + wv.w * __ldg(xp + iv.w);
            ssm[i] = s;
        }
        // stage weights w[k][o] for this c (coalesced from transposed copy)
        {
            const float* wp = wT + (size_t)c * (Kk * Onc);
#pragma unroll
            for (int k = 0; k < 9; k++)
                wsm[k * 256 + tid] = __ldg(wp + k * 256 + tid);
        }
        __syncthreads();

#pragma unroll
        for (int k = 0; k < 9; k++) {
            float4 wA = *(const float4*)(wsm + k * 256 + to * 8);
            float4 wB = *(const float4*)(wsm + k * 256 + to * 8 + 4);
            float4 sA = *(const float4*)(ssm + k * 64 + tp * 8);
            float4 sB = *(const float4*)(ssm + k * 64 + tp * 8 + 4);
            float wv[8] = {wA.x, wA.y, wA.z, wA.w, wB.x, wB.y, wB.z, wB.w};
            float sv[8] = {sA.x, sA.y, sA.z, sA.w, sB.x, sB.y, sB.z, sB.w};
#pragma unroll
            for (int i = 0; i < 8; i++)
#pragma unroll
                for (int j = 0; j < 8; j++)
                    acc[i][j] += wv[i] * sv[j];
        }
        __syncthreads();
    }

    // epilogue: bias + ReLU, write [B,O,H,W]
#pragma unroll
    for (int i = 0; i < 8; i++) {
        int o = to * 8 + i;
        float bv = __ldg(bias + o);
        float* op = out + ((size_t)(b * Onc + o) * Hh + (py0 + tp)) * Ww + px0;
#pragma unroll
        for (int j = 0; j < 8; j++) {
            float v = acc[i][j] + bv;
            op[j] = v > 0.f ? v : 0.f;
        }
    }
}

// ---------------------------------------------------------------------------
// Launch
// ---------------------------------------------------------------------------
extern "C" void kernel_launch(void* const* d_in, const int* in_sizes, int n_in,
                              void* d_out, int out_size)
{
    const float* x = (const float*)d_in[0];
    const float* w_off[3] = {(const float*)d_in[1], (const float*)d_in[5], (const float*)d_in[9]};
    const float* b_off[3] = {(const float*)d_in[2], (const float*)d_in[6], (const float*)d_in[10]};
    const float* wq[3]    = {(const float*)d_in[3], (const float*)d_in[7], (const float*)d_in[11]};
    const float* bias[3]  = {(const float*)d_in[4], (const float*)d_in[8], (const float*)d_in[12]};

    float *buf1, *buf2, *wT;
    cudaGetSymbolAddress((void**)&buf1, g_buf1);
    cudaGetSymbolAddress((void**)&buf2, g_buf2);
    cudaGetSymbolAddress((void**)&wT, g_wT);

    // Transpose main weights for all 3 layers
    for (int l = 0; l < 3; l++) {
        transpose_w_kernel<<<(Cc * Kk * Onc + 255) / 256, 256>>>(wq[l], wT + (size_t)l * Cc * Kk * Onc);
    }

    const float* src[3] = {x, buf1, buf2};
    float*       dst[3] = {buf1, buf2, (float*)d_out};

    for (int l = 0; l < 3; l++) {
        dcn_fused_kernel<<<dim3(64, Bn), 256>>>(src[l], w_off[l], b_off[l],
                                                wT + (size_t)l * Cc * Kk * Onc,
                                                bias[l], dst[l]);
    }
}

// round 3
// speedup vs baseline: 1.6096x; 1.1458x over previous
#include <cuda_runtime.h>
#include <math.h>

#define Bn 4
#define Cc 256
#define Onc 256
#define Hh 64
#define Ww 64
#define Kk 9
#define HW 4096

typedef unsigned long long u64;

// Scratch (static device arrays — no allocation)
__device__ float g_buf1[Bn * Cc * HW];          // layer0 output
__device__ float g_buf2[Bn * Cc * HW];          // layer1 output
__device__ float g_wT[3 * Cc * Kk * Onc];       // main weights [l][c][k][o]
__device__ float g_woT[3 * Cc * Kk * 28];       // offset weights [l][c][tap][28] (27 + pad)

// ---- packed f32x2 helpers -------------------------------------------------
#define FMA2(d, a, b)  asm("fma.rn.f32x2 %0, %1, %2, %0;" : "+l"(d) : "l"(a), "l"(b))
#define ADDP2(d, a)    asm("add.rn.f32x2 %0, %1, %0;" : "+l"(d) : "l"(a))

__device__ __forceinline__ u64 pack2(float lo, float hi) {
    u64 r; asm("mov.b64 %0, {%1,%2};" : "=l"(r) : "f"(lo), "f"(hi)); return r;
}
__device__ __forceinline__ float2 unpack2(u64 v) {
    float2 f; asm("mov.b64 {%0,%1}, %2;" : "=f"(f.x), "=f"(f.y) : "l"(v)); return f;
}

// ---------------------------------------------------------------------------
// Prep: transpose main-conv weights [O][C][3][3] -> [C][9][O]
// ---------------------------------------------------------------------------
__global__ void transpose_w_kernel(const float* __restrict__ w, float* __restrict__ wT)
{
    int idx = blockIdx.x * blockDim.x + threadIdx.x;
    if (idx >= Cc * Kk * Onc) return;
    int o = idx & (Onc - 1);
    int k = (idx >> 8) % Kk;
    int c = idx / (Kk * Onc);
    wT[idx] = w[((size_t)o * Cc + c) * Kk + k];
}

// Prep: transpose offset weights [27][C][3][3] -> [C][9][28] (padded)
__global__ void transpose_woff_kernel(const float* __restrict__ w, float* __restrict__ wT)
{
    int idx = blockIdx.x * blockDim.x + threadIdx.x;
    if (idx >= Cc * Kk * 28) return;
    int oc  = idx % 28;
    int tap = (idx / 28) % Kk;
    int c   = idx / (Kk * 28);
    wT[idx] = (oc < 27) ? w[((size_t)oc * Cc + c) * Kk + tap] : 0.f;
}

// ---------------------------------------------------------------------------
// Fused kernel: offset conv + bilinear sampling + GEMM + bias + ReLU.
// Block 256 threads, tile 8x8 pixels x 256 outputs. Grid (64, B).
// Phase 1: f32x2 offset conv, 16 channels per barrier round.
// Phase 2: f32x2 GEMM, thread tile 16o x 4p (o-paired accumulators),
//          2 channels per staging round.
// ---------------------------------------------------------------------------
__global__ __launch_bounds__(256, 2) void dcn_fused_kernel(
    const float* __restrict__ x,
    const float* __restrict__ w_offT,  // [C][9][28]
    const float* __restrict__ b_off,   // [27]
    const float* __restrict__ wT,      // [C][9][O]
    const float* __restrict__ bias,    // [O]
    float* __restrict__ out)
{
    __shared__ __align__(16) union {
        struct {
            float xs[16][120];      // 16 channels x 10x12 halo
            float wo[16 * 252];     // 16 channels x 9 taps x 28
        } p1;
        struct {
            float4 swgt[576];       // premultiplied bilinear weights
            int4   sidx[576];       // clamped gather indices
        } p2;
    } u1;
    __shared__ __align__(16) union {
        float om[2][64][28];        // reduced offset-conv partials
        struct {
            float ssm[2 * 576];     // sampled values, 2 channels
            float wsm[2 * 2304];    // weights, 2 channels
        } p2;
    } u2;

    int b   = blockIdx.y;
    int t   = blockIdx.x;             // 0..63
    int py0 = (t >> 3) * 8;
    int px0 = (t & 7) * 8;
    int tid = threadIdx.x;

    // ======================== Phase 1: offset conv ========================
    {
        int p   = tid & 63;
        int g   = tid >> 6;           // channel group 0..3
        int ppy = p >> 3;
        int ppx = p & 7;

        u64 aoff2[14];
#pragma unroll
        for (int j = 0; j < 14; j++) aoff2[j] = 0ull;

        for (int r = 0; r < 16; r++) {
            __syncthreads();
            // stage 16 channels' 10x10 halos (rows padded to 12)
            for (int i = tid; i < 1920; i += 256) {
                int ch  = i / 120;
                int rem = i - ch * 120;
                int rr  = rem / 12;
                int cc2 = rem - rr * 12;
                int c   = (r << 4) + ch;
                int gy  = py0 - 1 + rr;
                int gx  = px0 - 1 + cc2;
                float v = 0.f;
                if (cc2 < 10 && (unsigned)gy < (unsigned)Hh && (unsigned)gx < (unsigned)Ww)
                    v = __ldg(x + ((size_t)(b * Cc + c)) * HW + gy * Ww + gx);
                u1.p1.xs[ch][rem] = v;
            }
            // stage 16 channels' pre-transposed offset weights (coalesced)
            {
                const float4* wp4 = (const float4*)(w_offT + (size_t)(r << 4) * 252);
                float4* wo4 = (float4*)u1.p1.wo;
                for (int i = tid; i < 1008; i += 256) wo4[i] = wp4[i];
            }
            __syncthreads();

#pragma unroll
            for (int ci = 0; ci < 4; ci++) {
                int ch = (g << 2) + ci;
                const float* xrow = u1.p1.xs[ch];
                float xv[9];
#pragma unroll
                for (int rr = 0; rr < 3; rr++)
#pragma unroll
                    for (int cc = 0; cc < 3; cc++)
                        xv[rr * 3 + cc] = xrow[(ppy + rr) * 12 + ppx + cc];

#pragma unroll
                for (int tap = 0; tap < 9; tap++) {
                    u64 xt2 = pack2(xv[tap], xv[tap]);
                    const ulonglong2* wr = (const ulonglong2*)(u1.p1.wo + ch * 252 + tap * 28);
#pragma unroll
                    for (int j = 0; j < 7; j++) {
                        ulonglong2 wv2 = wr[j];
                        FMA2(aoff2[2 * j],     xt2, wv2.x);
                        FMA2(aoff2[2 * j + 1], xt2, wv2.y);
                    }
                }
            }
        }
        __syncthreads();
        // two-step cross-group reduction into u2.om[2][64][28]
        if (g >= 2) {
#pragma unroll
            for (int j = 0; j < 14; j++)
                *(u64*)&u2.om[g - 2][p][2 * j] = aoff2[j];
        }
        __syncthreads();
        if (g < 2) {
#pragma unroll
            for (int j = 0; j < 14; j++) {
                u64 tacc = *(u64*)&u2.om[g][p][2 * j];
                ADDP2(tacc, aoff2[j]);
                *(u64*)&u2.om[g][p][2 * j] = tacc;
            }
        }
        __syncthreads();
    }

    // ============= Coordinate / gather-weight precompute =============
    for (int i = tid; i < 576; i += 256) {
        int p = i & 63;
        int k = i >> 6;
        int gy = py0 + (p >> 3);
        int gx = px0 + (p & 7);
        float dy = __ldg(b_off + 2 * k)     + u2.om[0][p][2 * k]     + u2.om[1][p][2 * k];
        float dx = __ldg(b_off + 2 * k + 1) + u2.om[0][p][2 * k + 1] + u2.om[1][p][2 * k + 1];
        float mr = __ldg(b_off + 18 + k)    + u2.om[0][p][18 + k]    + u2.om[1][p][18 + k];
        float mv = 1.f / (1.f + expf(-mr));
        float ysv = (float)gy + (float)(k / 3 - 1) + dy;
        float xsv = (float)gx + (float)(k % 3 - 1) + dx;
        float y0f = floorf(ysv), x0f = floorf(xsv);
        float wy = ysv - y0f, wx = xsv - x0f;
        int y0 = (int)y0f, x0 = (int)x0f;
        int y1 = y0 + 1, x1 = x0 + 1;
        bool vy0 = (y0 >= 0) && (y0 < Hh);
        bool vy1 = (y1 >= 0) && (y1 < Hh);
        bool vx0 = (x0 >= 0) && (x0 < Ww);
        bool vx1 = (x1 >= 0) && (x1 < Ww);
        int y0c = min(max(y0, 0), Hh - 1), y1c = min(max(y1, 0), Hh - 1);
        int x0c = min(max(x0, 0), Ww - 1), x1c = min(max(x1, 0), Ww - 1);
        float4 wv;
        wv.x = (vy0 && vx0) ? mv * (1.f - wy) * (1.f - wx) : 0.f;
        wv.y = (vy0 && vx1) ? mv * (1.f - wy) * wx         : 0.f;
        wv.z = (vy1 && vx0) ? mv * wy * (1.f - wx)         : 0.f;
        wv.w = (vy1 && vx1) ? mv * wy * wx                 : 0.f;
        int4 iv;
        iv.x = y0c * Ww + x0c;
        iv.y = y0c * Ww + x1c;
        iv.z = y1c * Ww + x0c;
        iv.w = y1c * Ww + x1c;
        u1.p2.swgt[i] = wv;
        u1.p2.sidx[i] = iv;
    }
    __syncthreads();   // om reads done; U2 may now be reused for ssm/wsm

    // ================= Phase 2: sampling + GEMM + epilogue =================
    int to = tid >> 4;   // 0..15 -> o-base = to*16
    int tp = tid & 15;   // 0..15 -> p-base = tp*4

    u64 acc2[8][4];
#pragma unroll
    for (int i = 0; i < 8; i++)
#pragma unroll
        for (int j = 0; j < 4; j++) acc2[i][j] = 0ull;

    for (int c0 = 0; c0 < Cc; c0 += 2) {
        const float* xp0 = x + ((size_t)(b * Cc + c0)) * HW;
        // stage sampled values for 2 channels: ssm[cc*576 + j]
        for (int i = tid; i < 1152; i += 256) {
            int cc = (i >= 576);
            int j  = i - (cc ? 576 : 0);
            const float* xp = xp0 + cc * HW;
            float4 wv = u1.p2.swgt[j];
            int4   iv = u1.p2.sidx[j];
            float s = wv.x * __ldg(xp + iv.x) + wv.y * __ldg(xp + iv.y)
                    + wv.z * __ldg(xp + iv.z) + wv.w * __ldg(xp + iv.w);
            u2.p2.ssm[i] = s;
        }
        // stage weights for 2 channels (coalesced float4 copy: 4608 floats)
        {
            const float4* wp4 = (const float4*)(wT + (size_t)c0 * (Kk * Onc));
            float4* wsm4 = (float4*)u2.p2.wsm;
            for (int i = tid; i < 1152; i += 256) wsm4[i] = wp4[i];
        }
        __syncthreads();

#pragma unroll
        for (int cc = 0; cc < 2; cc++) {
#pragma unroll
            for (int k = 0; k < 9; k++) {
                const float* wr = u2.p2.wsm + cc * 2304 + k * 256 + (to << 4);
                ulonglong2 w01 = *(const ulonglong2*)(wr);
                ulonglong2 w23 = *(const ulonglong2*)(wr + 4);
                ulonglong2 w45 = *(const ulonglong2*)(wr + 8);
                ulonglong2 w67 = *(const ulonglong2*)(wr + 12);
                float4 sv = *(const float4*)(u2.p2.ssm + cc * 576 + k * 64 + (tp << 2));
                u64 sp[4];
                sp[0] = pack2(sv.x, sv.x);
                sp[1] = pack2(sv.y, sv.y);
                sp[2] = pack2(sv.z, sv.z);
                sp[3] = pack2(sv.w, sv.w);
                u64 wp[8] = {w01.x, w01.y, w23.x, w23.y, w45.x, w45.y, w67.x, w67.y};
#pragma unroll
                for (int op = 0; op < 8; op++)
#pragma unroll
                    for (int j = 0; j < 4; j++)
                        FMA2(acc2[op][j], wp[op], sp[j]);
            }
        }
        __syncthreads();
    }

    // epilogue: bias + ReLU, vectorized stores
    {
        int row = tp >> 1;
        int cb  = (tp & 1) << 2;
#pragma unroll
        for (int op = 0; op < 8; op++) {
            int o0 = (to << 4) + (op << 1);
            float bv0 = __ldg(bias + o0);
            float bv1 = __ldg(bias + o0 + 1);
            float2 v0 = unpack2(acc2[op][0]);
            float2 v1 = unpack2(acc2[op][1]);
            float2 v2 = unpack2(acc2[op][2]);
            float2 v3 = unpack2(acc2[op][3]);
            float4 lo, hi;
            lo.x = fmaxf(v0.x + bv0, 0.f); lo.y = fmaxf(v1.x + bv0, 0.f);
            lo.z = fmaxf(v2.x + bv0, 0.f); lo.w = fmaxf(v3.x + bv0, 0.f);
            hi.x = fmaxf(v0.y + bv1, 0.f); hi.y = fmaxf(v1.y + bv1, 0.f);
            hi.z = fmaxf(v2.y + bv1, 0.f); hi.w = fmaxf(v3.y + bv1, 0.f);
            size_t base0 = ((size_t)(b * Onc + o0) * Hh + py0 + row) * Ww + px0 + cb;
            size_t base1 = base0 + (size_t)Hh * Ww;
            *(float4*)(out + base0) = lo;
            *(float4*)(out + base1) = hi;
        }
    }
}

// ---------------------------------------------------------------------------
// Launch
// ---------------------------------------------------------------------------
extern "C" void kernel_launch(void* const* d_in, const int* in_sizes, int n_in,
                              void* d_out, int out_size)
{
    const float* x = (const float*)d_in[0];
    const float* w_off[3] = {(const float*)d_in[1], (const float*)d_in[5], (const float*)d_in[9]};
    const float* b_off[3] = {(const float*)d_in[2], (const float*)d_in[6], (const float*)d_in[10]};
    const float* wq[3]    = {(const float*)d_in[3], (const float*)d_in[7], (const float*)d_in[11]};
    const float* bias[3]  = {(const float*)d_in[4], (const float*)d_in[8], (const float*)d_in[12]};

    float *buf1, *buf2, *wT, *woT;
    cudaGetSymbolAddress((void**)&buf1, g_buf1);
    cudaGetSymbolAddress((void**)&buf2, g_buf2);
    cudaGetSymbolAddress((void**)&wT, g_wT);
    cudaGetSymbolAddress((void**)&woT, g_woT);

    for (int l = 0; l < 3; l++) {
        transpose_w_kernel<<<(Cc * Kk * Onc + 255) / 256, 256>>>(wq[l], wT + (size_t)l * Cc * Kk * Onc);
        transpose_woff_kernel<<<(Cc * Kk * 28 + 255) / 256, 256>>>(w_off[l], woT + (size_t)l * Cc * Kk * 28);
    }

    const float* src[3] = {x, buf1, buf2};
    float*       dst[3] = {buf1, buf2, (float*)d_out};

    for (int l = 0; l < 3; l++) {
        dcn_fused_kernel<<<dim3(64, Bn), 256>>>(src[l],
                                                woT + (size_t)l * Cc * Kk * 28,
                                                b_off[l],
                                                wT + (size_t)l * Cc * Kk * Onc,
                                                bias[l], dst[l]);
    }
}